// round 9
// baseline (speedup 1.0000x reference)
#include <cuda_runtime.h>
#include <cuda_bf16.h>

// Fast Walsh-Hadamard transform, 16384 rows x 1024 fp32.
// y[row] = FWHT(x[row]) / 32, emitted as interleaved (real, 0) pairs.
//
// One warp per 4 consecutive rows, 32 values/thread, software-pipelined:
// the 16 LDG.64 for row i+1 are issued before the long compute of row i,
// so 3/4 of all row-load latencies are fully hidden under shfl/FADD work.
// Per row: lane l owns elements {2l + b + 64j}:
//   stride 1          -> register butterfly (b pair)
//   strides 2..32     -> 5 shfl.xor stages
//   strides 64..512   -> register butterflies over j bits
// No shared memory, no barriers. Loads 16x LDG.64 coalesced; stores 16x
// STG.128 coalesced with the zero-imag interleave folded in.

#define DIMN 1024
#define WPB  4            // warps per block -> 128 threads
#define RPW  4            // rows per warp (pipeline depth 2)

__device__ __forceinline__ void bf(float &x, float &y) {
    float s = x + y;
    y = x - y;
    x = s;
}

__global__ void __launch_bounds__(32 * WPB, 6)
fwht_kernel(const float2* __restrict__ xin, float4* __restrict__ yout, int nrows)
{
    const int l   = threadIdx.x & 31;
    const int w   = threadIdx.x >> 5;
    const int gw  = blockIdx.x * WPB + w;
    const int row0 = gw * RPW;
    if (row0 >= nrows) return;

    // ---- prefetch row0: 16 independent coalesced LDG.64 ----
    float2 p[16];
    {
        const float2* in = xin + (size_t)row0 * (DIMN / 2) + l;
        #pragma unroll
        for (int j = 0; j < 16; j++) p[j] = in[32 * j];
    }

    #pragma unroll
    for (int it = 0; it < RPW; it++) {
        const int row = row0 + it;
        if (row >= nrows) return;

        // take ownership of the prefetched row
        float a[16], b[16];
        #pragma unroll
        for (int j = 0; j < 16; j++) { a[j] = p[j].x; b[j] = p[j].y; }

        // issue next row's loads NOW; compute below hides their latency
        if (it + 1 < RPW && row + 1 < nrows) {
            const float2* in = xin + (size_t)(row + 1) * (DIMN / 2) + l;
            #pragma unroll
            for (int j = 0; j < 16; j++) p[j] = in[32 * j];
        }

        // ---- stride 1 (register, b-pair) ----
        #pragma unroll
        for (int j = 0; j < 16; j++) bf(a[j], b[j]);

        // ---- strides 2,4,8,16,32 via shfl.xor on lane bits ----
        #pragma unroll
        for (int d = 1; d <= 16; d <<= 1) {
            const bool up = (l & d) != 0;
            #pragma unroll
            for (int j = 0; j < 16; j++) {
                float oa = __shfl_xor_sync(0xffffffffu, a[j], d);
                float ob = __shfl_xor_sync(0xffffffffu, b[j], d);
                a[j] = up ? (oa - a[j]) : (a[j] + oa);
                b[j] = up ? (ob - b[j]) : (b[j] + ob);
            }
        }

        // ---- strides 64,128,256,512: butterflies over j bits ----
        #pragma unroll
        for (int s = 1; s <= 8; s <<= 1) {
            #pragma unroll
            for (int j = 0; j < 16; j++) {
                if ((j & s) == 0) {
                    bf(a[j], a[j + s]);
                    bf(b[j], b[j + s]);
                }
            }
        }

        // ---- scaled, interleaved (real, 0) stores; 16 coalesced STG.128 ----
        const float sc = 0.03125f;   // 1/sqrt(1024)
        float4* out = yout + (size_t)row * (2 * DIMN / 4) + l;
        #pragma unroll
        for (int j = 0; j < 16; j++) {
            __stcs(out + 32 * j, make_float4(a[j] * sc, 0.0f, b[j] * sc, 0.0f));
        }
    }
}

extern "C" void kernel_launch(void* const* d_in, const int* in_sizes, int n_in,
                              void* d_out, int out_size)
{
    const float* x = (const float*)d_in[0];   // [B, S, 1024] fp32
    // d_in[1] is H; unused — the transform is computed directly.
    float* out = (float*)d_out;               // [B, S, 1024, 2] fp32

    const int nrows = in_sizes[0] / DIMN;     // 16384
    const int rows_per_block = WPB * RPW;
    const int grid = (nrows + rows_per_block - 1) / rows_per_block;

    fwht_kernel<<<grid, 32 * WPB>>>((const float2*)x, (float4*)out, nrows);
}